// round 1
// baseline (speedup 1.0000x reference)
#include <cuda_runtime.h>
#include <cuda_bf16.h>

#define HD   64
#define MAXN 8192
#define LDP  132   // padded shared stride for gram tiles (128 + 4)

// Scratch (no allocations allowed): h state and aggregation buffer.
__device__ float g_h[MAXN * HD];
__device__ float g_agg[MAXN * HD];

// ---------------------------------------------------------------------------
// h = relu(features @ W_node + b_node)    [N,F]@[F,H]
// 256 threads = 4 rows x 64 cols
// ---------------------------------------------------------------------------
__global__ void k_embed(const float* __restrict__ feat,
                        const float* __restrict__ Wn,
                        const float* __restrict__ bn,
                        int N, int F) {
    __shared__ float sW[16 * HD];
    __shared__ float sb[HD];
    int tid = threadIdx.x;
    for (int i = tid; i < F * HD; i += blockDim.x) sW[i] = Wn[i];
    if (tid < HD) sb[tid] = bn[tid];
    __syncthreads();
    int row = blockIdx.x * 4 + (tid >> 6);
    int col = tid & 63;
    if (row < N) {
        float acc = sb[col];
        const float* fr = feat + (size_t)row * F;
        for (int f = 0; f < F; f++) acc = fmaf(fr[f], sW[f * HD + col], acc);
        g_h[row * HD + col] = fmaxf(acc, 0.f);
    }
}

// ---------------------------------------------------------------------------
// agg = 0
// ---------------------------------------------------------------------------
__global__ void k_zero(int n4) {
    int i = blockIdx.x * blockDim.x + threadIdx.x;
    if (i < n4) ((float4*)g_agg)[i] = make_float4(0.f, 0.f, 0.f, 0.f);
}

// ---------------------------------------------------------------------------
// agg[dst] += h[src]; 16 threads per edge, float4 chunk each (4 scalar REDs)
// ---------------------------------------------------------------------------
__global__ void k_scatter(const int* __restrict__ edges, int E) {
    int t = blockIdx.x * blockDim.x + threadIdx.x;
    int e = t >> 4;
    if (e >= E) return;
    int c = (t & 15) << 2;
    int src = edges[2 * e];
    int dst = edges[2 * e + 1];
    float4 v = *(const float4*)(g_h + src * HD + c);
    float* d = g_agg + dst * HD + c;
    atomicAdd(d + 0, v.x);
    atomicAdd(d + 1, v.y);
    atomicAdd(d + 2, v.z);
    atomicAdd(d + 3, v.w);
}

// ---------------------------------------------------------------------------
// h = relu((h + agg) @ W_conv + b_conv)   [N,64]@[64,64], in-place safe
// 512 threads = 8 rows x 64 cols
// ---------------------------------------------------------------------------
__global__ void k_update(const float* __restrict__ Wc,
                         const float* __restrict__ bc, int N) {
    __shared__ float sW[HD * HD];
    __shared__ float sx[8][HD];
    int tid = threadIdx.x;
    for (int i = tid; i < HD * HD; i += 512) sW[i] = Wc[i];
    int lr = tid >> 6, col = tid & 63;
    int row = blockIdx.x * 8 + lr;
    float xv = 0.f;
    if (row < N) xv = g_h[row * HD + col] + g_agg[row * HD + col];
    sx[lr][col] = xv;
    __syncthreads();
    if (row < N) {
        float acc = bc[col];
#pragma unroll 8
        for (int k = 0; k < HD; k++) acc = fmaf(sx[lr][k], sW[k * HD + col], acc);
        g_h[row * HD + col] = fmaxf(acc, 0.f);
    }
}

// ---------------------------------------------------------------------------
// S = h @ h^T; out[1] = S; out[0] = mask_i * mask_j * S  (mask = nodes==2)
// 128x128 tile, 256 threads, 8x8 micro-tile, K=64 resident in shared.
// ---------------------------------------------------------------------------
__global__ void __launch_bounds__(256, 2)
k_gram(const int* __restrict__ nodes, float* __restrict__ out, int N) {
    extern __shared__ float sm[];
    float* As = sm;             // [HD][LDP], transposed: As[k][i]
    float* Bs = sm + HD * LDP;  // [HD][LDP]
    int tid = threadIdx.x;
    int row0 = blockIdx.y * 128;
    int col0 = blockIdx.x * 128;

    // Load both 128x64 tiles transposed into shared (float4 global reads)
    for (int idx = tid; idx < 128 * 16; idx += 256) {
        int r = idx >> 4;
        int c = (idx & 15) << 2;
        float4 va = *(const float4*)(g_h + (row0 + r) * HD + c);
        As[(c + 0) * LDP + r] = va.x;
        As[(c + 1) * LDP + r] = va.y;
        As[(c + 2) * LDP + r] = va.z;
        As[(c + 3) * LDP + r] = va.w;
        float4 vb = *(const float4*)(g_h + (col0 + r) * HD + c);
        Bs[(c + 0) * LDP + r] = vb.x;
        Bs[(c + 1) * LDP + r] = vb.y;
        Bs[(c + 2) * LDP + r] = vb.z;
        Bs[(c + 3) * LDP + r] = vb.w;
    }
    __syncthreads();

    int tx = tid & 15, ty = tid >> 4;
    int ri = ty * 8, cj = tx * 8;

    float acc[8][8];
#pragma unroll
    for (int i = 0; i < 8; i++)
#pragma unroll
        for (int j = 0; j < 8; j++) acc[i][j] = 0.f;

#pragma unroll 4
    for (int k = 0; k < HD; k++) {
        float a[8], b[8];
        *(float4*)(a)     = *(float4*)&As[k * LDP + ri];
        *(float4*)(a + 4) = *(float4*)&As[k * LDP + ri + 4];
        *(float4*)(b)     = *(float4*)&Bs[k * LDP + cj];
        *(float4*)(b + 4) = *(float4*)&Bs[k * LDP + cj + 4];
#pragma unroll
        for (int i = 0; i < 8; i++)
#pragma unroll
            for (int j = 0; j < 8; j++)
                acc[i][j] = fmaf(a[i], b[j], acc[i][j]);
    }

    float mj[8];
#pragma unroll
    for (int j = 0; j < 8; j++) mj[j] = (nodes[col0 + cj + j] == 2) ? 1.f : 0.f;

    size_t NN = (size_t)N * N;
#pragma unroll
    for (int i = 0; i < 8; i++) {
        int r = row0 + ri + i;
        float mi = (nodes[r] == 2) ? 1.f : 0.f;
        float* p0 = out + (size_t)r * N + (col0 + cj);       // function_deps
        float* p1 = p0 + NN;                                  // similarity
        float4 v1a = make_float4(acc[i][0], acc[i][1], acc[i][2], acc[i][3]);
        float4 v1b = make_float4(acc[i][4], acc[i][5], acc[i][6], acc[i][7]);
        float4 v0a = make_float4(acc[i][0] * mi * mj[0], acc[i][1] * mi * mj[1],
                                 acc[i][2] * mi * mj[2], acc[i][3] * mi * mj[3]);
        float4 v0b = make_float4(acc[i][4] * mi * mj[4], acc[i][5] * mi * mj[5],
                                 acc[i][6] * mi * mj[6], acc[i][7] * mi * mj[7]);
        *(float4*)(p1)     = v1a;
        *(float4*)(p1 + 4) = v1b;
        *(float4*)(p0)     = v0a;
        *(float4*)(p0 + 4) = v0b;
    }
}

// ---------------------------------------------------------------------------
extern "C" void kernel_launch(void* const* d_in, const int* in_sizes, int n_in,
                              void* d_out, int out_size) {
    const float* feat  = (const float*)d_in[0];
    const float* Wn    = (const float*)d_in[1];
    const float* bn    = (const float*)d_in[2];
    const float* Wc    = (const float*)d_in[3];
    const float* bc    = (const float*)d_in[4];
    const int*   nodes = (const int*)d_in[5];
    const int*   edges = (const int*)d_in[6];
    float* out = (float*)d_out;

    int N = in_sizes[5];
    int F = in_sizes[0] / N;
    int E = in_sizes[6] / 2;

    k_embed<<<(N + 3) / 4, 256>>>(feat, Wn, bn, N, F);

    for (int it = 0; it < 2; it++) {
        int n4 = N * HD / 4;
        k_zero<<<(n4 + 255) / 256, 256>>>(n4);
        long long T = (long long)E * 16;
        k_scatter<<<(int)((T + 255) / 256), 256>>>(edges, E);
        k_update<<<(N + 7) / 8, 512>>>(Wc, bc, N);
    }

    int smem = 2 * HD * LDP * (int)sizeof(float);  // 67584 bytes
    cudaFuncSetAttribute(k_gram, cudaFuncAttributeMaxDynamicSharedMemorySize, smem);
    dim3 grid(N / 128, N / 128);
    k_gram<<<grid, 256, smem>>>(nodes, out, N);
}

// round 16
// speedup vs baseline: 2.0916x; 2.0916x over previous
#include <cuda_runtime.h>
#include <cuda_bf16.h>
#include <cstdint>

#define HD   64
#define MAXN 8192
#define KLD  68    // padded k-stride for gram smem tiles

__device__ float g_h[MAXN * HD];
__device__ float g_agg[MAXN * HD];

// ---------------------------------------------------------------------------
// h = relu(features @ W_node + b_node)
// ---------------------------------------------------------------------------
__global__ void k_embed(const float* __restrict__ feat,
                        const float* __restrict__ Wn,
                        const float* __restrict__ bn,
                        int N, int F) {
    __shared__ float sW[16 * HD];
    __shared__ float sb[HD];
    int tid = threadIdx.x;
    for (int i = tid; i < F * HD; i += blockDim.x) sW[i] = Wn[i];
    if (tid < HD) sb[tid] = bn[tid];
    __syncthreads();
    int row = blockIdx.x * 4 + (tid >> 6);
    int col = tid & 63;
    if (row < N) {
        float acc = sb[col];
        const float* fr = feat + (size_t)row * F;
        for (int f = 0; f < F; f++) acc = fmaf(fr[f], sW[f * HD + col], acc);
        g_h[row * HD + col] = fmaxf(acc, 0.f);
    }
}

__global__ void k_zero(int n4) {
    int i = blockIdx.x * blockDim.x + threadIdx.x;
    if (i < n4) ((float4*)g_agg)[i] = make_float4(0.f, 0.f, 0.f, 0.f);
}

// ---------------------------------------------------------------------------
// agg[dst] += h[src]; 16 threads/edge, one red.v4 each
// ---------------------------------------------------------------------------
__global__ void k_scatter(const int* __restrict__ edges, int E) {
    int t = blockIdx.x * blockDim.x + threadIdx.x;
    int e = t >> 4;
    if (e >= E) return;
    int c = (t & 15) << 2;
    int2 ed = *(const int2*)(edges + 2 * e);
    float4 v = *(const float4*)(g_h + ed.x * HD + c);
    float* d = g_agg + ed.y * HD + c;
    asm volatile("red.global.add.v4.f32 [%0], {%1, %2, %3, %4};"
                 :: "l"(d), "f"(v.x), "f"(v.y), "f"(v.z), "f"(v.w)
                 : "memory");
}

// ---------------------------------------------------------------------------
// h = relu((h + agg) @ W_conv + b_conv), 32 rows per block
// ---------------------------------------------------------------------------
__global__ void k_update(const float* __restrict__ Wc,
                         const float* __restrict__ bc, int N) {
    __shared__ float sW[HD * HD];
    __shared__ float sb[HD];
    __shared__ float sx[8][HD];
    int tid = threadIdx.x;
    for (int i = tid; i < HD * HD; i += 512) sW[i] = Wc[i];
    if (tid < HD) sb[tid] = bc[tid];
    int lr = tid >> 6, col = tid & 63;
    __syncthreads();
    for (int g = 0; g < 4; g++) {
        int row = blockIdx.x * 32 + g * 8 + lr;
        float xv = 0.f;
        if (row < N) xv = g_h[row * HD + col] + g_agg[row * HD + col];
        sx[lr][col] = xv;
        __syncthreads();
        if (row < N) {
            float acc = sb[col];
#pragma unroll 8
            for (int k = 0; k < HD; k++) acc = fmaf(sx[lr][k], sW[k * HD + col], acc);
            g_h[row * HD + col] = fmaxf(acc, 0.f);
        }
        __syncthreads();
    }
}

// ---------------------------------------------------------------------------
// Gram via tf32 mma.sync m16n8k8: S = h @ h^T
// out[1] = S; out[0] = mask_i*mask_j*S
// 128x128 block tile, 8 warps (2x4), 64x32 per warp.
// ---------------------------------------------------------------------------
__device__ __forceinline__ uint32_t f2tf32(float x) {
    uint32_t r;
    asm("cvt.rna.tf32.f32 %0, %1;" : "=r"(r) : "f"(x));
    return r;
}

__global__ void __launch_bounds__(256, 2)
k_gram(const int* __restrict__ nodes, float* __restrict__ out, int N) {
    extern __shared__ float sm[];
    float* As = sm;                    // [128][KLD] tf32 bits
    float* Bs = sm + 128 * KLD;        // [128][KLD]
    float* mA = sm + 2 * 128 * KLD;    // [128] row mask
    float* mB = mA + 128;              // [128] col mask

    int tid = threadIdx.x;
    int row0 = blockIdx.y * 128;
    int col0 = blockIdx.x * 128;

    // fill tiles (tf32-rounded) + masks
    for (int idx = tid; idx < 128 * 16; idx += 256) {
        int r = idx >> 4;
        int c = (idx & 15) << 2;
        float4 va = *(const float4*)(g_h + (row0 + r) * HD + c);
        float* pa = As + r * KLD + c;
        pa[0] = __uint_as_float(f2tf32(va.x));
        pa[1] = __uint_as_float(f2tf32(va.y));
        pa[2] = __uint_as_float(f2tf32(va.z));
        pa[3] = __uint_as_float(f2tf32(va.w));
        float4 vb = *(const float4*)(g_h + (col0 + r) * HD + c);
        float* pb = Bs + r * KLD + c;
        pb[0] = __uint_as_float(f2tf32(vb.x));
        pb[1] = __uint_as_float(f2tf32(vb.y));
        pb[2] = __uint_as_float(f2tf32(vb.z));
        pb[3] = __uint_as_float(f2tf32(vb.w));
    }
    if (tid < 128) mA[tid] = (nodes[row0 + tid] == 2) ? 1.f : 0.f;
    else           mB[tid - 128] = (nodes[col0 + tid - 128] == 2) ? 1.f : 0.f;
    __syncthreads();

    int wid = tid >> 5, lane = tid & 31;
    int g = lane >> 2, tg = lane & 3;          // groupID, thread-in-group
    int warp_m = (wid & 1) * 64;               // 0 or 64
    int warp_n = (wid >> 1) * 32;              // 0,32,64,96

    float d[4][4][4];                          // [mt][nt][reg]
#pragma unroll
    for (int i = 0; i < 4; i++)
#pragma unroll
        for (int j = 0; j < 4; j++)
#pragma unroll
            for (int q = 0; q < 4; q++) d[i][j][q] = 0.f;

    for (int s = 0; s < 8; s++) {              // K = 64, k-step 8
        int k0 = s * 8;
        uint32_t a[4][4], b[4][2];
#pragma unroll
        for (int mt = 0; mt < 4; mt++) {
            const float* p = As + (warp_m + mt * 16 + g) * KLD + k0;
            a[mt][0] = __float_as_uint(p[tg]);
            a[mt][1] = __float_as_uint(p[8 * KLD + tg]);
            a[mt][2] = __float_as_uint(p[tg + 4]);
            a[mt][3] = __float_as_uint(p[8 * KLD + tg + 4]);
        }
#pragma unroll
        for (int nt = 0; nt < 4; nt++) {
            const float* p = Bs + (warp_n + nt * 8 + g) * KLD + k0;
            b[nt][0] = __float_as_uint(p[tg]);
            b[nt][1] = __float_as_uint(p[tg + 4]);
        }
#pragma unroll
        for (int mt = 0; mt < 4; mt++)
#pragma unroll
            for (int nt = 0; nt < 4; nt++) {
                asm volatile(
                    "mma.sync.aligned.m16n8k8.row.col.f32.tf32.tf32.f32 "
                    "{%0,%1,%2,%3}, {%4,%5,%6,%7}, {%8,%9}, {%0,%1,%2,%3};"
                    : "+f"(d[mt][nt][0]), "+f"(d[mt][nt][1]),
                      "+f"(d[mt][nt][2]), "+f"(d[mt][nt][3])
                    : "r"(a[mt][0]), "r"(a[mt][1]), "r"(a[mt][2]), "r"(a[mt][3]),
                      "r"(b[nt][0]), "r"(b[nt][1]));
            }
    }

    size_t NN = (size_t)N * N;
#pragma unroll
    for (int mt = 0; mt < 4; mt++) {
        int rl0 = warp_m + mt * 16 + g;
        int r0 = row0 + rl0;
        float mi0 = mA[rl0], mi1 = mA[rl0 + 8];
#pragma unroll
        for (int nt = 0; nt < 4; nt++) {
            int cl = warp_n + nt * 8 + tg * 2;
            int c = col0 + cl;
            float mj0 = mB[cl], mj1 = mB[cl + 1];
            float* p1 = out + NN + (size_t)r0 * N + c;       // similarity
            float* p0 = out + (size_t)r0 * N + c;            // function_deps
            *(float2*)p1 = make_float2(d[mt][nt][0], d[mt][nt][1]);
            *(float2*)p0 = make_float2(d[mt][nt][0] * mi0 * mj0,
                                       d[mt][nt][1] * mi0 * mj1);
            *(float2*)(p1 + (size_t)8 * N) = make_float2(d[mt][nt][2], d[mt][nt][3]);
            *(float2*)(p0 + (size_t)8 * N) = make_float2(d[mt][nt][2] * mi1 * mj0,
                                                         d[mt][nt][3] * mi1 * mj1);
        }
    }
}

// ---------------------------------------------------------------------------
extern "C" void kernel_launch(void* const* d_in, const int* in_sizes, int n_in,
                              void* d_out, int out_size) {
    const float* feat  = (const float*)d_in[0];
    const float* Wn    = (const float*)d_in[1];
    const float* bn    = (const float*)d_in[2];
    const float* Wc    = (const float*)d_in[3];
    const float* bc    = (const float*)d_in[4];
    const int*   nodes = (const int*)d_in[5];
    const int*   edges = (const int*)d_in[6];
    float* out = (float*)d_out;

    int N = in_sizes[5];
    int F = in_sizes[0] / N;
    int E = in_sizes[6] / 2;

    k_embed<<<(N + 3) / 4, 256>>>(feat, Wn, bn, N, F);

    for (int it = 0; it < 2; it++) {
        int n4 = N * HD / 4;
        k_zero<<<(n4 + 255) / 256, 256>>>(n4);
        long long T = (long long)E * 16;
        k_scatter<<<(int)((T + 255) / 256), 256>>>(edges, E);
        k_update<<<(N + 31) / 32, 512>>>(Wc, bc, N);
    }

    int smem = (2 * 128 * KLD + 256) * (int)sizeof(float);  // 70656 B
    cudaFuncSetAttribute(k_gram, cudaFuncAttributeMaxDynamicSharedMemorySize, smem);
    dim3 grid(N / 128, N / 128);
    k_gram<<<grid, 256, smem>>>(nodes, out, N);
}